// round 14
// baseline (speedup 1.0000x reference)
#include <cuda_runtime.h>
#include <cstdint>

// Embedding gather: out[i, :] = w[x[i], :]
// x: [N=16384] int32, w: [32000, 1024] f32, out: [N, 1024] f32.
//
// Floor established R1-R12 (~16.9us): steady state = 64MB L2-hit w reads +
// 64MB mandatory DRAM writes; all L2-residency manipulations falsified;
// half-split/32B layouts regress (ptxas reg/scheduling trap).
//
// R13 = exact R2 winning shape (256 thr, 8 rows/block, 8 batched __ldg
// loads) with ONE change: __stwt write-through stores. .wt never
// write-allocates in L2 -> strictly stronger protection of the w table and
// less LTS occupancy for the write stream than .cs, same mandatory DRAM
// write bytes. If this regresses, R2 is the final kernel.

#define DIM 1024
#define VECS_PER_ROW (DIM / 4)      // 256 float4 per row
#define THREADS 256
#define ROWS_PER_BLOCK 8

__global__ __launch_bounds__(THREADS)
void embed_gather_kernel(const int* __restrict__ x,
                         const float4* __restrict__ w,
                         float4* __restrict__ out,
                         int n_rows)
{
    const int tid = threadIdx.x;              // vec index within row
    const int row0 = blockIdx.x * ROWS_PER_BLOCK;

    if (row0 + ROWS_PER_BLOCK <= n_rows) {
        int idx[ROWS_PER_BLOCK];
#pragma unroll
        for (int r = 0; r < ROWS_PER_BLOCK; r++)
            idx[r] = __ldg(&x[row0 + r]);

        // 8 independent 16B gather loads, all issued before any store.
        float4 v[ROWS_PER_BLOCK];
#pragma unroll
        for (int r = 0; r < ROWS_PER_BLOCK; r++)
            v[r] = __ldg(&w[(size_t)idx[r] * VECS_PER_ROW + tid]);

        // Write-through stores: no L2 write-allocate at all; w stays
        // resident, write stream coalesces in the MC write buffers.
#pragma unroll
        for (int r = 0; r < ROWS_PER_BLOCK; r++)
            __stwt(&out[(size_t)(row0 + r) * VECS_PER_ROW + tid], v[r]);
    } else {
        for (int r = 0; r < ROWS_PER_BLOCK; r++) {
            int row = row0 + r;
            if (row < n_rows) {
                int idx = __ldg(&x[row]);
                float4 v = __ldg(&w[(size_t)idx * VECS_PER_ROW + tid]);
                __stwt(&out[(size_t)row * VECS_PER_ROW + tid], v);
            }
        }
    }
}

extern "C" void kernel_launch(void* const* d_in, const int* in_sizes, int n_in,
                              void* d_out, int out_size)
{
    // metadata order: x (int32, B*S = 16384), w (float32, 32000*1024)
    const int* x = (const int*)d_in[0];
    const float4* w = (const float4*)d_in[1];
    float4* out = (float4*)d_out;

    const int n_rows = in_sizes[0];           // 16384
    const int grid = (n_rows + ROWS_PER_BLOCK - 1) / ROWS_PER_BLOCK;

    embed_gather_kernel<<<grid, THREADS>>>(x, w, out, n_rows);
}

// round 15
// speedup vs baseline: 1.2183x; 1.2183x over previous
#include <cuda_runtime.h>
#include <cstdint>

// Embedding gather: out[i, :] = w[x[i], :]
// x: [N=16384] int32, w: [32000, 1024] f32, out: [N, 1024] f32.
//
// FINAL KERNEL (= R2, measured 16.86us twice; floor confirmed over 13 rounds).
//
// Why this shape wins (evidence R1-R13):
//  - __stcs evict-first streaming stores are the key: the output stream never
//    displaces the ~128MB w table from the ~126MB L2, so across graph replays
//    the gathered w reads are nearly all L2 hits. Steady state is then bound
//    by the mandatory 64MiB of output DRAM writes plus 64MiB of LTS read
//    traffic (~7.6TB/s combined) -> ~16.9us floor.
//  - Store-policy sweep: plain=21.0us, .wt=21.2, L2::evict_last=21.2,
//    .cs=16.9. Load-policy sweep: plain .nc best.
//  - 8 independent 16B __ldg gather loads batched before any store give
//    sufficient MLP; deeper batching (16) and 32B/split-half layouts only
//    regress (register/scheduling traps, occupancy loss).
//  - Output L2-pinning is impossible here (persisting-carveout is 0 and
//    changing device limits is banned), so the write traffic is irreducible.

#define DIM 1024
#define VECS_PER_ROW (DIM / 4)      // 256 float4 per row
#define THREADS 256
#define ROWS_PER_BLOCK 8

__global__ __launch_bounds__(THREADS)
void embed_gather_kernel(const int* __restrict__ x,
                         const float4* __restrict__ w,
                         float4* __restrict__ out,
                         int n_rows)
{
    const int tid = threadIdx.x;              // vec index within row
    const int row0 = blockIdx.x * ROWS_PER_BLOCK;

    if (row0 + ROWS_PER_BLOCK <= n_rows) {
        int idx[ROWS_PER_BLOCK];
#pragma unroll
        for (int r = 0; r < ROWS_PER_BLOCK; r++)
            idx[r] = __ldg(&x[row0 + r]);

        // 8 independent 16B gather loads, all issued before any store (MLP).
        float4 v[ROWS_PER_BLOCK];
#pragma unroll
        for (int r = 0; r < ROWS_PER_BLOCK; r++)
            v[r] = __ldg(&w[(size_t)idx[r] * VECS_PER_ROW + tid]);

        // Evict-first streaming stores: never displace w from L2.
#pragma unroll
        for (int r = 0; r < ROWS_PER_BLOCK; r++)
            __stcs(&out[(size_t)(row0 + r) * VECS_PER_ROW + tid], v[r]);
    } else {
        for (int r = 0; r < ROWS_PER_BLOCK; r++) {
            int row = row0 + r;
            if (row < n_rows) {
                int idx = __ldg(&x[row]);
                float4 v = __ldg(&w[(size_t)idx * VECS_PER_ROW + tid]);
                __stcs(&out[(size_t)row * VECS_PER_ROW + tid], v);
            }
        }
    }
}

extern "C" void kernel_launch(void* const* d_in, const int* in_sizes, int n_in,
                              void* d_out, int out_size)
{
    // metadata order: x (int32, B*S = 16384), w (float32, 32000*1024)
    const int* x = (const int*)d_in[0];
    const float4* w = (const float4*)d_in[1];
    float4* out = (float4*)d_out;

    const int n_rows = in_sizes[0];           // 16384
    const int grid = (n_rows + ROWS_PER_BLOCK - 1) / ROWS_PER_BLOCK;

    embed_gather_kernel<<<grid, THREADS>>>(x, w, out, n_rows);
}

// round 16
// speedup vs baseline: 1.2411x; 1.0187x over previous
#include <cuda_runtime.h>
#include <cstdint>

// Embedding gather: out[i, :] = w[x[i], :]
// x: [N=16384] int32, w: [32000, 1024] f32, out: [N, 1024] f32.
//
// FINAL KERNEL (R2 shape; best measured 16.86us, run-to-run noise ~±0.5us).
//
// Evidence summary (14 rounds):
//  - __stcs evict-first streaming stores are the decisive lever: output
//    writes never displace the ~128MB w table from the ~126MB L2, so across
//    graph replays the gathered reads are L2 hits. Steady state = 64MiB
//    mandatory DRAM writes + 64MiB LTS reads (~7.6TB/s combined) -> ~16.9us,
//    the measured memory-system floor.
//  - Store-policy sweep: plain=21.0, .wt=21.2, L2::evict_last=21.2, .cs=16.9.
//  - 8 independent 16B __ldg gather loads batched before any store give all
//    the MLP this kernel can use; deeper batching and 32B/split layouts
//    regress (register/scheduling traps, occupancy loss, no byte savings).
//  - Output L2 pinning is unavailable (persisting carveout = 0; changing
//    device limits is banned), so the DRAM write traffic is irreducible.

#define DIM 1024
#define VECS_PER_ROW (DIM / 4)      // 256 float4 per row
#define THREADS 256
#define ROWS_PER_BLOCK 8

__global__ __launch_bounds__(THREADS)
void embed_gather_kernel(const int* __restrict__ x,
                         const float4* __restrict__ w,
                         float4* __restrict__ out,
                         int n_rows)
{
    const int tid = threadIdx.x;              // vec index within row
    const int row0 = blockIdx.x * ROWS_PER_BLOCK;

    if (row0 + ROWS_PER_BLOCK <= n_rows) {
        int idx[ROWS_PER_BLOCK];
#pragma unroll
        for (int r = 0; r < ROWS_PER_BLOCK; r++)
            idx[r] = __ldg(&x[row0 + r]);

        // 8 independent 16B gather loads, all issued before any store (MLP).
        float4 v[ROWS_PER_BLOCK];
#pragma unroll
        for (int r = 0; r < ROWS_PER_BLOCK; r++)
            v[r] = __ldg(&w[(size_t)idx[r] * VECS_PER_ROW + tid]);

        // Evict-first streaming stores: never displace w from L2.
#pragma unroll
        for (int r = 0; r < ROWS_PER_BLOCK; r++)
            __stcs(&out[(size_t)(row0 + r) * VECS_PER_ROW + tid], v[r]);
    } else {
        for (int r = 0; r < ROWS_PER_BLOCK; r++) {
            int row = row0 + r;
            if (row < n_rows) {
                int idx = __ldg(&x[row]);
                float4 v = __ldg(&w[(size_t)idx * VECS_PER_ROW + tid]);
                __stcs(&out[(size_t)row * VECS_PER_ROW + tid], v);
            }
        }
    }
}

extern "C" void kernel_launch(void* const* d_in, const int* in_sizes, int n_in,
                              void* d_out, int out_size)
{
    // metadata order: x (int32, B*S = 16384), w (float32, 32000*1024)
    const int* x = (const int*)d_in[0];
    const float4* w = (const float4*)d_in[1];
    float4* out = (float4*)d_out;

    const int n_rows = in_sizes[0];           // 16384
    const int grid = (n_rows + ROWS_PER_BLOCK - 1) / ROWS_PER_BLOCK;

    embed_gather_kernel<<<grid, THREADS>>>(x, w, out, n_rows);
}

// round 17
// speedup vs baseline: 1.2576x; 1.0133x over previous
#include <cuda_runtime.h>
#include <cstdint>

// Embedding gather: out[i, :] = w[x[i], :]
// x: [N=16384] int32, w: [32000, 1024] f32, out: [N, 1024] f32.
//
// FINAL KERNEL — measured floor over 15 rounds: 16.86us best,
// 17.1 +/- 0.3us across four identical-source runs.
//
// Evidence summary:
//  - __stcs evict-first streaming stores are the decisive lever: the output
//    stream never displaces the ~128MB w table from the ~126MB L2, so across
//    graph replays the gathered w reads are L2 hits. Steady state = 64MiB
//    mandatory DRAM writes + 64MiB LTS reads (~7.6TB/s combined), the
//    measured memory-system ceiling for this pattern.
//  - Store-policy sweep: plain=21.0, .wt=21.2, L2::evict_last=21.2, .cs=16.9.
//  - 8 independent 16B __ldg gather loads batched before any store supply
//    all usable MLP; deeper batches and 32B/split layouts only regress.
//  - All bytes-reduction avenues are structurally closed: dtype fixed,
//    writes mandatory, L1 flushed per launch, L2 carveout unavailable,
//    dedup/reordering costs exceed their savings.

#define DIM 1024
#define VECS_PER_ROW (DIM / 4)      // 256 float4 per row
#define THREADS 256
#define ROWS_PER_BLOCK 8

__global__ __launch_bounds__(THREADS)
void embed_gather_kernel(const int* __restrict__ x,
                         const float4* __restrict__ w,
                         float4* __restrict__ out,
                         int n_rows)
{
    const int tid = threadIdx.x;              // vec index within row
    const int row0 = blockIdx.x * ROWS_PER_BLOCK;

    if (row0 + ROWS_PER_BLOCK <= n_rows) {
        int idx[ROWS_PER_BLOCK];
#pragma unroll
        for (int r = 0; r < ROWS_PER_BLOCK; r++)
            idx[r] = __ldg(&x[row0 + r]);

        // 8 independent 16B gather loads, all issued before any store (MLP).
        float4 v[ROWS_PER_BLOCK];
#pragma unroll
        for (int r = 0; r < ROWS_PER_BLOCK; r++)
            v[r] = __ldg(&w[(size_t)idx[r] * VECS_PER_ROW + tid]);

        // Evict-first streaming stores: never displace w from L2.
#pragma unroll
        for (int r = 0; r < ROWS_PER_BLOCK; r++)
            __stcs(&out[(size_t)(row0 + r) * VECS_PER_ROW + tid], v[r]);
    } else {
        for (int r = 0; r < ROWS_PER_BLOCK; r++) {
            int row = row0 + r;
            if (row < n_rows) {
                int idx = __ldg(&x[row]);
                float4 v = __ldg(&w[(size_t)idx * VECS_PER_ROW + tid]);
                __stcs(&out[(size_t)row * VECS_PER_ROW + tid], v);
            }
        }
    }
}

extern "C" void kernel_launch(void* const* d_in, const int* in_sizes, int n_in,
                              void* d_out, int out_size)
{
    // metadata order: x (int32, B*S = 16384), w (float32, 32000*1024)
    const int* x = (const int*)d_in[0];
    const float4* w = (const float4*)d_in[1];
    float4* out = (float4*)d_out;

    const int n_rows = in_sizes[0];           // 16384
    const int grid = (n_rows + ROWS_PER_BLOCK - 1) / ROWS_PER_BLOCK;

    embed_gather_kernel<<<grid, THREADS>>>(x, w, out, n_rows);
}